// round 9
// baseline (speedup 1.0000x reference)
#include <cuda_runtime.h>
#include <cuda_bf16.h>
#include <cstdint>

#define DF 128          // feature dim
#define DH 512          // hidden dim
#define MAXN 10000      // nodes
#define MAXG 128        // >= n_graphs (100)
#define EPW 32          // edges per half-warp strip

// -------- static device scratch (no allocations allowed) --------
__device__ float g_tmp[MAXN * DH];          // relu(nodes@W1+b1)
__device__ float g_h[MAXN * DF];            // final node features (fp32, exact)
__device__ __nv_bfloat16 g_hb[MAXN * DF];   // bf16 mirror for edge gather (2.5MB)
__device__ float g_wsum[MAXG];
__device__ float g_esum[MAXG];
__device__ int   g_eoff[MAXG + 1];
__device__ int   g_nid[MAXG];

// ============================================================================
// Kernel 0: prefix sums + zero accumulators (runs every replay)
// ============================================================================
__global__ void prefix_kernel(const int* __restrict__ n_node,
                              const int* __restrict__ n_edge, int G) {
    int t = threadIdx.x;
    if (t < MAXG) { g_wsum[t] = 0.f; g_esum[t] = 0.f; }
    if (t == 0) {
        int ea = 0, na = 0;
        g_eoff[0] = 0;
        for (int g = 0; g < G; g++) {
            ea += n_edge[g]; g_eoff[g + 1] = ea;
            na += n_node[g]; g_nid[g] = na - 1;
        }
    }
}

// ============================================================================
// Tiled SGEMM (known-good SIMT): C = act(A@B + bias)
// 64x64 tile, BK=32, 256 threads, 4x4 micro-tile.
// If Cb != nullptr, also writes a bf16 mirror of C.
// ============================================================================
__global__ __launch_bounds__(256)
void gemm_bias_act(const float* __restrict__ A, const float* __restrict__ B,
                   const float* __restrict__ bias, float* __restrict__ C,
                   __nv_bfloat16* __restrict__ Cb,
                   int M, int N, int K, int doRelu) {
    const int BM = 64, BN = 64, BK = 32;
    __shared__ float As[BM][BK + 4];
    __shared__ float Bs[BK][BN + 4];

    int tid = threadIdx.x;
    int tx = tid & 15;
    int ty = tid >> 4;
    int row0 = blockIdx.y * BM;
    int col0 = blockIdx.x * BN;

    float acc[4][4] = {};

    for (int k0 = 0; k0 < K; k0 += BK) {
        #pragma unroll
        for (int i = 0; i < 2; i++) {
            int lin = tid + i * 256;
            int r = lin >> 3;
            int c4 = (lin & 7) * 4;
            int row = row0 + r;
            float4 v = make_float4(0.f, 0.f, 0.f, 0.f);
            if (row < M)
                v = *(const float4*)(A + (size_t)row * K + k0 + c4);
            *(float4*)&As[r][c4] = v;
        }
        #pragma unroll
        for (int i = 0; i < 2; i++) {
            int lin = tid + i * 256;
            int kk = lin >> 4;
            int c4 = (lin & 15) * 4;
            float4 v = *(const float4*)(B + (size_t)(k0 + kk) * N + col0 + c4);
            *(float4*)&Bs[kk][c4] = v;
        }
        __syncthreads();

        #pragma unroll
        for (int k = 0; k < BK; k++) {
            float4 b4 = *(const float4*)&Bs[k][tx * 4];
            #pragma unroll
            for (int i = 0; i < 4; i++) {
                float a = As[ty * 4 + i][k];
                acc[i][0] += a * b4.x;
                acc[i][1] += a * b4.y;
                acc[i][2] += a * b4.z;
                acc[i][3] += a * b4.w;
            }
        }
        __syncthreads();
    }

    #pragma unroll
    for (int i = 0; i < 4; i++) {
        int row = row0 + ty * 4 + i;
        if (row >= M) continue;
        float o[4];
        #pragma unroll
        for (int j = 0; j < 4; j++) {
            int col = col0 + tx * 4 + j;
            float v = acc[i][j] + bias[col];
            if (doRelu) v = fmaxf(v, 0.f);
            o[j] = v;
            C[(size_t)row * N + col] = v;
        }
        if (Cb) {
            __nv_bfloat162 p0 = __floats2bfloat162_rn(o[0], o[1]);
            __nv_bfloat162 p1 = __floats2bfloat162_rn(o[2], o[3]);
            uint2 pk = make_uint2(*(unsigned*)&p0, *(unsigned*)&p1);
            *(uint2*)(Cb + (size_t)row * N + col0 + tx * 4) = pk;
        }
    }
}

// ============================================================================
// Edge kernel v5: half-warp per edge (2 edges per warp instruction).
// Lane l (0..15 within half-warp) owns 8 bf16 features = 16B -> LDG.128.
// Each half-warp runs an independent strip of EPW edges with its own
// graph-segment bookkeeping; reduction is 4 shuffles over width 16.
// ============================================================================
__global__ __launch_bounds__(256)
void edge_kernel(const float* __restrict__ ew,
                 const int* __restrict__ snd, const int* __restrict__ rcv,
                 int E, int G) {
    int lane16 = threadIdx.x & 15;
    int hw = blockIdx.x * 16 + (threadIdx.x >> 4);   // global half-warp id
    int base = hw * EPW;
    if (base >= E) return;
    int end = min(base + EPW, E);

    int lo = 0, hi = G;
    while (hi - lo > 1) {
        int mid = (lo + hi) >> 1;
        if (g_eoff[mid] <= base) lo = mid; else hi = mid;
    }
    int gid = lo;
    int bnd = g_eoff[gid + 1];

    const __nv_bfloat16* __restrict__ hb = g_hb;
    float acc = 0.f, wacc = 0.f;
    int e = base;
    for (;;) {
        int seg = min(end, bnd);
        #pragma unroll 4
        for (; e < seg; e++) {
            int s = __ldg(snd + e);
            int r = __ldg(rcv + e);
            float w = __ldg(ew + e);
            uint4 av = *(const uint4*)(hb + (size_t)s * DF + lane16 * 8);
            uint4 bv = *(const uint4*)(hb + (size_t)r * DF + lane16 * 8);
            unsigned d0, d1, d2, d3;
            asm("sub.rn.bf16x2 %0, %1, %2;" : "=r"(d0) : "r"(av.x), "r"(bv.x));
            asm("sub.rn.bf16x2 %0, %1, %2;" : "=r"(d1) : "r"(av.y), "r"(bv.y));
            asm("sub.rn.bf16x2 %0, %1, %2;" : "=r"(d2) : "r"(av.z), "r"(bv.z));
            asm("sub.rn.bf16x2 %0, %1, %2;" : "=r"(d3) : "r"(av.w), "r"(bv.w));
            // bf16 -> fp32 exactly via bit placement (no F2F)
            float f0 = __uint_as_float(d0 << 16);
            float f1 = __uint_as_float(d0 & 0xFFFF0000u);
            float f2 = __uint_as_float(d1 << 16);
            float f3 = __uint_as_float(d1 & 0xFFFF0000u);
            float f4 = __uint_as_float(d2 << 16);
            float f5 = __uint_as_float(d2 & 0xFFFF0000u);
            float f6 = __uint_as_float(d3 << 16);
            float f7 = __uint_as_float(d3 & 0xFFFF0000u);
            float t = f0 * f0;
            t = fmaf(f1, f1, t);
            t = fmaf(f2, f2, t);
            t = fmaf(f3, f3, t);
            t = fmaf(f4, f4, t);
            t = fmaf(f5, f5, t);
            t = fmaf(f6, f6, t);
            t = fmaf(f7, f7, t);
            acc = fmaf(w, t, acc);
            if (lane16 == 0) wacc += w;
        }
        float v = acc;
        #pragma unroll
        for (int off = 8; off; off >>= 1)
            v += __shfl_xor_sync(0xffffffffu, v, off);
        if (lane16 == 0) {
            atomicAdd(&g_esum[gid], v);
            atomicAdd(&g_wsum[gid], wacc);
        }
        if (e >= end) break;
        acc = 0.f; wacc = 0.f;
        gid++;
        bnd = g_eoff[gid + 1];
    }
}

// ============================================================================
// Output kernel: gather node_out rows (exact fp32); block 0 computes loss.
// ============================================================================
__global__ void out_kernel(float* __restrict__ out, int G, int lossIdx) {
    int g = blockIdx.x;
    int t = threadIdx.x;
    if (g < G)
        out[g * DF + t] = g_h[(size_t)g_nid[g] * DF + t];
    if (g == 0) {
        __shared__ float red[128];
        float term = 0.f;
        if (t < G) {
            float w = g_wsum[t];
            term = (w != 0.f) ? (g_esum[t] / w) : 0.f;
        }
        red[t] = term;
        __syncthreads();
        #pragma unroll
        for (int s = 64; s; s >>= 1) {
            if (t < s) red[t] += red[t + s];
            __syncthreads();
        }
        if (t == 0) out[lossIdx] = red[0] / (float)G;
    }
}

// ============================================================================
extern "C" void kernel_launch(void* const* d_in, const int* in_sizes, int n_in,
                              void* d_out, int out_size) {
    const float* nodes     = (const float*)d_in[0];
    const float* edges     = (const float*)d_in[1];
    const int*   senders   = (const int*)d_in[2];
    const int*   receivers = (const int*)d_in[3];
    const int*   n_node    = (const int*)d_in[4];
    const int*   n_edge    = (const int*)d_in[5];
    const float* W1        = (const float*)d_in[6];
    const float* b1        = (const float*)d_in[7];
    const float* W2        = (const float*)d_in[8];
    const float* b2        = (const float*)d_in[9];
    float* out = (float*)d_out;

    int M = in_sizes[0] / DF;
    int E = in_sizes[2];
    int G = in_sizes[4];

    void *p_tmp = nullptr, *p_h = nullptr, *p_hb = nullptr;
    cudaGetSymbolAddress(&p_tmp, g_tmp);
    cudaGetSymbolAddress(&p_h, g_h);
    cudaGetSymbolAddress(&p_hb, g_hb);

    prefix_kernel<<<1, 128>>>(n_node, n_edge, G);

    dim3 g1(DH / 64, (M + 63) / 64);
    gemm_bias_act<<<g1, 256>>>(nodes, W1, b1, (float*)p_tmp, nullptr,
                               M, DH, DF, 1);

    dim3 g2(DF / 64, (M + 63) / 64);
    gemm_bias_act<<<g2, 256>>>((float*)p_tmp, W2, b2, (float*)p_h,
                               (__nv_bfloat16*)p_hb, M, DF, DH, 0);

    // 16 half-warps per 256-thread block, EPW edges each
    int eblocks = (E + EPW * 16 - 1) / (EPW * 16);
    edge_kernel<<<eblocks, 256>>>(edges, senders, receivers, E, G);

    out_kernel<<<G, 128>>>(out, G, out_size - 1);
}